// round 1
// baseline (speedup 1.0000x reference)
#include <cuda_runtime.h>
#include <math.h>
#include <stdint.h>

// ---------------------------------------------------------------------------
// GDER: out[b] = mean( Rx^2 + Ry^2 ) over valid 498x498 map.
// Because sum(Gy) is cancellation noise (~1e-17), Gy/sum(Gy) taps are ~1e15 and
// Ry^2 dominates Rx^2 (and the +1e-7 box term) by >1e16 relative — so we only
// compute the Gy path, as a separable conv:  Gy = A(y) * B(x).
// The 1/sum(Gy) scale is folded into the vertical (antisymmetric) taps.
// sum(Gy) is replicated on the host with numpy's exact float64 pairwise order.
// ---------------------------------------------------------------------------

#define NB        64
#define W         512
#define OUTW      498
#define TILE_ROWS 30
#define TILES_Y   17      // 17*30 = 510 >= 498

struct Weights {
    float hw[8];   // horizontal symmetric taps: hw[j], j=0..6 pair weights, hw[7] center
    float vw[7];   // vertical antisymmetric taps (scaled by 1/sum(Gy)); tap 7 is exactly 0
};

__device__ double g_partials[NB * TILES_Y];

__global__ __launch_bounds__(128) void gder_conv_kernel(const float* __restrict__ x, Weights wt)
{
    const int t     = threadIdx.x;
    const int tileY = blockIdx.x;
    const int b     = blockIdx.y;
    const int y0    = tileY * TILE_ROWS;
    const float* __restrict__ img = x + (size_t)b * W * W;

    __shared__ float  vbuf[2][544];   // 512 cols + 32 pad (windows read up to col 527)
    __shared__ double red[128];

    // zero the pad region of both buffers (read by masked-out lanes)
    if (t < 32) { vbuf[0][512 + t] = 0.f; vbuf[1][512 + t] = 0.f; }

    const int c4 = t * 4;             // this thread's 4 columns: c4..c4+3

    // register ring: 15 rows x 4 cols of input history
    float4 h[15];
    #pragma unroll
    for (int i = 0; i < 14; ++i)
        h[i] = *reinterpret_cast<const float4*>(img + (size_t)(y0 + i) * W + c4);
    h[14] = make_float4(0.f, 0.f, 0.f, 0.f);

    float facc = 0.f;
    int buf = 0;

    for (int g = 0; g < 2; ++g) {
        #pragma unroll
        for (int p = 0; p < 15; ++p) {
            const int yo = g * 15 + p;        // output row within tile
            const int gr = y0 + 14 + yo;      // newest input row needed
            float4 nv = make_float4(0.f, 0.f, 0.f, 0.f);
            if (gr < W)
                nv = *reinterpret_cast<const float4*>(img + (size_t)gr * W + c4);
            h[(14 + p) % 15] = nv;

            // vertical (antisymmetric): v = sum_{k<7} vw[k]*(row_k - row_{14-k})
            float sx = 0.f, sy = 0.f, sz = 0.f, sw = 0.f;
            #pragma unroll
            for (int k = 0; k < 7; ++k) {
                const float4 a  = h[(p + k)      % 15];
                const float4 bb = h[(p + 14 - k) % 15];
                sx = fmaf(wt.vw[k], a.x - bb.x, sx);
                sy = fmaf(wt.vw[k], a.y - bb.y, sy);
                sz = fmaf(wt.vw[k], a.z - bb.z, sz);
                sw = fmaf(wt.vw[k], a.w - bb.w, sw);
            }
            *reinterpret_cast<float4*>(&vbuf[buf][c4]) = make_float4(sx, sy, sz, sw);
            __syncthreads();

            // horizontal (symmetric) on the staged v row: 5x LDS.128 window
            float win[20];
            #pragma unroll
            for (int q = 0; q < 5; ++q) {
                const float4 wv = *reinterpret_cast<const float4*>(&vbuf[buf][c4 + 4 * q]);
                win[4 * q + 0] = wv.x; win[4 * q + 1] = wv.y;
                win[4 * q + 2] = wv.z; win[4 * q + 3] = wv.w;
            }
            const int orow = y0 + yo;
            if (orow < OUTW) {
                #pragma unroll
                for (int c = 0; c < 4; ++c) {
                    float o = wt.hw[7] * win[c + 7];
                    #pragma unroll
                    for (int j = 0; j < 7; ++j)
                        o = fmaf(wt.hw[j], win[c + j] + win[c + 14 - j], o);
                    if (c4 + c < OUTW)
                        facc = fmaf(o, o, facc);
                }
            }
            buf ^= 1;
        }
    }

    // deterministic block reduction in double
    red[t] = (double)facc;
    __syncthreads();
    #pragma unroll
    for (int s = 64; s > 0; s >>= 1) {
        if (t < s) red[t] += red[t + s];
        __syncthreads();
    }
    if (t == 0) g_partials[b * TILES_Y + tileY] = red[0];
}

__global__ void gder_reduce_kernel(float* __restrict__ out)
{
    const int b = threadIdx.x;
    if (b < NB) {
        double s = 0.0;
        #pragma unroll
        for (int i = 0; i < TILES_Y; ++i)
            s += g_partials[b * TILES_Y + i];
        out[b] = (float)(s * (1.0 / ((double)OUTW * (double)OUTW)));
    }
}

// ---------------------------------------------------------------------------
// Host side: replicate numpy float64 semantics exactly.
// ---------------------------------------------------------------------------

// numpy's pairwise_sum for contiguous float64 (PW_BLOCKSIZE = 128)
static double np_pairwise(const double* a, int n)
{
    if (n < 8) {
        double res = 0.0;
        for (int i = 0; i < n; ++i) res += a[i];
        return res;
    }
    else if (n <= 128) {
        double r[8];
        for (int j = 0; j < 8; ++j) r[j] = a[j];
        int i;
        for (i = 8; i < n - (n % 8); i += 8)
            for (int j = 0; j < 8; ++j) r[j] += a[i + j];
        double res = ((r[0] + r[1]) + (r[2] + r[3])) + ((r[4] + r[5]) + (r[6] + r[7]));
        for (; i < n; ++i) res += a[i];
        return res;
    }
    else {
        int n2 = n / 2;
        n2 -= n2 % 8;
        return np_pairwise(a, n2) + np_pairwise(a + n2, n - n2);
    }
}

extern "C" void kernel_launch(void* const* d_in, const int* in_sizes, int n_in,
                              void* d_out, int out_size)
{
    (void)in_sizes; (void)n_in; (void)out_size;
    const float* x  = (const float*)d_in[0];
    float*      out = (float*)d_out;

    // --- replicate _make_kernels() in float64, exactly as numpy evaluates it ---
    const double sig     = 7.0 / 2.5;              // N=15//2=7; sig = N/2.5
    const double sig2    = pow(sig, 2.0);          // sig ** 2 (CPython float_pow -> libm pow)
    const double twosig2 = 2.0 * sig2;             // 2 * sig ** 2
    const double denomG  = (2.0 * M_PI) * sig;     // 2 * np.pi * sig

    double Gy[225];
    for (int i = 0; i < 15; ++i) {
        const int yy = i - 7;
        for (int j = 0; j < 15; ++j) {
            const int xx = j - 7;
            const double G = exp((double)(-(xx * xx + yy * yy)) / twosig2) / denomG;
            Gy[i * 15 + j] = ((double)(-yy) * G) / sig2;   // -y * G / sig**2
        }
    }
    const double s = np_pairwise(Gy, 225);         // np.sum(Gy), numpy pairwise order

    Weights wt;
    // horizontal factor B(x) = exp(-x^2/(2 sig^2)) / (2 pi sig)   (symmetric)
    for (int j = 0; j < 8; ++j) {
        const int xx = j - 7;
        wt.hw[j] = (float)(exp((double)(-(xx * xx)) / twosig2) / denomG);
    }
    // vertical factor A(y) = (-y) exp(-y^2/(2 sig^2)) / sig^2 / sum(Gy)  (antisymmetric)
    for (int k = 0; k < 7; ++k) {
        const int yy = k - 7;
        const double A = (((double)(-yy) * exp((double)(-(yy * yy)) / twosig2)) / sig2) / s;
        wt.vw[k] = (float)A;
    }

    dim3 grid(TILES_Y, NB);
    gder_conv_kernel<<<grid, 128>>>(x, wt);
    gder_reduce_kernel<<<1, 64>>>(out);
}

// round 2
// speedup vs baseline: 1.0774x; 1.0774x over previous
#include <cuda_runtime.h>
#include <math.h>
#include <stdint.h>

// ---------------------------------------------------------------------------
// GDER: out[b] = mean( Rx^2 + Ry^2 ) over valid 498x498 map.
// sum(Gy) is cancellation noise (~1e-17) => Gy/sum(Gy) taps ~1e15 and Ry^2
// dominates everything else by >1e16 relative. So only the Gy path is
// computed, as a separable conv: Gy = A(y) * B(x), with 1/sum(Gy) folded into
// the vertical taps. sum(Gy) replicated on host in numpy's exact f64 pairwise
// order (validated R1: rel_err 8.7e-8).
//
// R2: packed f32x2 math (2x fma-pipe throughput). Lane pairing = (col i,
// col i+256) so horizontal window shifts stay element-aligned. Reduction
// fused into the conv kernel (last-block-per-batch), removing the 6.1us
// second launch.
// ---------------------------------------------------------------------------

#define NB        64
#define W         512
#define OUTW      498
#define TILE_ROWS 30
#define TILES_Y   17      // 17*30 = 510 >= 498

typedef unsigned long long u64;

struct Weights {
    float hw[8];   // horizontal symmetric taps: hw[0..6] pair weights, hw[7] center
    float vw[7];   // vertical antisymmetric taps (scaled by 1/sum(Gy))
};

__device__ double g_partials[NB * TILES_Y];
__device__ int    g_count[NB];   // zero-initialized; self-resetting

// ---- f32x2 packed helpers (sm_100+) ----
__device__ __forceinline__ u64 pack2(float lo, float hi) {
    u64 r; asm("mov.b64 %0, {%1, %2};" : "=l"(r) : "f"(lo), "f"(hi)); return r;
}
__device__ __forceinline__ void unpack2(u64 v, float& lo, float& hi) {
    asm("mov.b64 {%0, %1}, %2;" : "=f"(lo), "=f"(hi) : "l"(v));
}
__device__ __forceinline__ u64 fma2(u64 a, u64 b, u64 c) {
    u64 d; asm("fma.rn.f32x2 %0, %1, %2, %3;" : "=l"(d) : "l"(a), "l"(b), "l"(c)); return d;
}
__device__ __forceinline__ u64 add2(u64 a, u64 b) {
    u64 d; asm("add.rn.f32x2 %0, %1, %2;" : "=l"(d) : "l"(a), "l"(b)); return d;
}
__device__ __forceinline__ u64 mul2(u64 a, u64 b) {
    u64 d; asm("mul.rn.f32x2 %0, %1, %2;" : "=l"(d) : "l"(a), "l"(b)); return d;
}

__global__ __launch_bounds__(128) void gder_kernel(const float* __restrict__ x,
                                                   Weights wt,
                                                   float* __restrict__ out)
{
    const int t     = threadIdx.x;
    const int tileY = blockIdx.x;
    const int b     = blockIdx.y;
    const int y0    = tileY * TILE_ROWS;
    const float* __restrict__ img = x + (size_t)b * W * W;

    // vertical results, packed (v[i], v[i+256]); entries 256..269 = (v[256+i], 0) pad
    __shared__ __align__(16) u64 vbuf[2][272];
    __shared__ double red[128];

    // broadcast packed weights
    u64 hw2[8], vp[7], vn[7];
    #pragma unroll
    for (int j = 0; j < 8; ++j) hw2[j] = pack2(wt.hw[j], wt.hw[j]);
    #pragma unroll
    for (int k = 0; k < 7; ++k) {
        vp[k] = pack2( wt.vw[k],  wt.vw[k]);
        vn[k] = pack2(-wt.vw[k], -wt.vw[k]);
    }

    const int c = 2 * t;   // packed stream indices c, c+1; lanes = (col, col+256)

    // register ring: 15 rows of 2 packed streams
    u64 h0[15], h1[15];
    #pragma unroll
    for (int i = 0; i < 14; ++i) {
        const float2 L = *reinterpret_cast<const float2*>(img + (size_t)(y0 + i) * W + c);
        const float2 R = *reinterpret_cast<const float2*>(img + (size_t)(y0 + i) * W + c + 256);
        h0[i] = pack2(L.x, R.x);
        h1[i] = pack2(L.y, R.y);
    }
    h0[14] = 0ull; h1[14] = 0ull;

    u64 facc = 0ull;
    int buf = 0;

    for (int g = 0; g < 2; ++g) {
        #pragma unroll
        for (int p = 0; p < 15; ++p) {
            const int yo = g * 15 + p;       // output row within tile
            const int gr = y0 + 14 + yo;     // newest input row
            u64 n0 = 0ull, n1 = 0ull;
            if (gr < W) {
                const float2 L = *reinterpret_cast<const float2*>(img + (size_t)gr * W + c);
                const float2 R = *reinterpret_cast<const float2*>(img + (size_t)gr * W + c + 256);
                n0 = pack2(L.x, R.x);
                n1 = pack2(L.y, R.y);
            }
            h0[(14 + p) % 15] = n0;
            h1[(14 + p) % 15] = n1;

            // vertical (antisymmetric): s = sum_k vw[k]*row_k - vw[k]*row_{14-k}
            u64 s0 = 0ull, s1 = 0ull;
            #pragma unroll
            for (int k = 0; k < 7; ++k) {
                s0 = fma2(vp[k], h0[(p + k) % 15], s0);
                s0 = fma2(vn[k], h0[(p + 14 - k) % 15], s0);
                s1 = fma2(vp[k], h1[(p + k) % 15], s1);
                s1 = fma2(vn[k], h1[(p + 14 - k) % 15], s1);
            }
            *reinterpret_cast<ulonglong2*>(&vbuf[buf][c]) = make_ulonglong2(s0, s1);
            if (t < 7) {   // extension: (hi lane value, 0) for window wrap
                float lo0, hi0, lo1, hi1;
                unpack2(s0, lo0, hi0);
                unpack2(s1, lo1, hi1);
                vbuf[buf][256 + c]     = pack2(hi0, 0.f);
                vbuf[buf][256 + c + 1] = pack2(hi1, 0.f);
            }
            __syncthreads();

            // horizontal (symmetric), packed, 2 outputs per thread
            if (y0 + yo < OUTW) {
                u64 win[16];
                #pragma unroll
                for (int q = 0; q < 8; ++q) {
                    const ulonglong2 v2 =
                        *reinterpret_cast<const ulonglong2*>(&vbuf[buf][c + 2 * q]);
                    win[2 * q]     = v2.x;
                    win[2 * q + 1] = v2.y;
                }
                #pragma unroll
                for (int k = 0; k < 2; ++k) {
                    u64 o = mul2(hw2[7], win[k + 7]);
                    #pragma unroll
                    for (int j = 0; j < 7; ++j)
                        o = fma2(hw2[j], add2(win[k + j], win[k + 14 - j]), o);
                    // hi lane = output col 256+c+k; invalid beyond 497 (c+k > 241)
                    if (t > 120) o &= 0x00000000FFFFFFFFull;
                    facc = fma2(o, o, facc);
                }
            }
            __syncthreads();
            buf ^= 1;
        }
    }

    // deterministic block reduction in double
    {
        float flo, fhi;
        unpack2(facc, flo, fhi);
        red[t] = (double)flo + (double)fhi;
    }
    __syncthreads();
    #pragma unroll
    for (int s = 64; s > 0; s >>= 1) {
        if (t < s) red[t] += red[t + s];
        __syncthreads();
    }
    if (t == 0) {
        g_partials[b * TILES_Y + tileY] = red[0];
        __threadfence();
        const int old = atomicAdd(&g_count[b], 1);
        if (old == TILES_Y - 1) {   // last block for this batch: fixed-order final sum
            __threadfence();
            double s = 0.0;
            #pragma unroll
            for (int i = 0; i < TILES_Y; ++i)
                s += __ldcg(&g_partials[b * TILES_Y + i]);
            out[b] = (float)(s * (1.0 / ((double)OUTW * (double)OUTW)));
            g_count[b] = 0;         // reset for next graph replay
        }
    }
}

// ---------------------------------------------------------------------------
// Host side: replicate numpy float64 semantics exactly (validated in R1).
// ---------------------------------------------------------------------------

// numpy's pairwise_sum for contiguous float64 (PW_BLOCKSIZE = 128)
static double np_pairwise(const double* a, int n)
{
    if (n < 8) {
        double res = 0.0;
        for (int i = 0; i < n; ++i) res += a[i];
        return res;
    }
    else if (n <= 128) {
        double r[8];
        for (int j = 0; j < 8; ++j) r[j] = a[j];
        int i;
        for (i = 8; i < n - (n % 8); i += 8)
            for (int j = 0; j < 8; ++j) r[j] += a[i + j];
        double res = ((r[0] + r[1]) + (r[2] + r[3])) + ((r[4] + r[5]) + (r[6] + r[7]));
        for (; i < n; ++i) res += a[i];
        return res;
    }
    else {
        int n2 = n / 2;
        n2 -= n2 % 8;
        return np_pairwise(a, n2) + np_pairwise(a + n2, n - n2);
    }
}

extern "C" void kernel_launch(void* const* d_in, const int* in_sizes, int n_in,
                              void* d_out, int out_size)
{
    (void)in_sizes; (void)n_in; (void)out_size;
    const float* x  = (const float*)d_in[0];
    float*      out = (float*)d_out;

    const double sig     = 7.0 / 2.5;              // N=15//2=7; sig = N/2.5
    const double sig2    = pow(sig, 2.0);          // sig ** 2 (CPython float_pow -> libm pow)
    const double twosig2 = 2.0 * sig2;
    const double denomG  = (2.0 * M_PI) * sig;

    double Gy[225];
    for (int i = 0; i < 15; ++i) {
        const int yy = i - 7;
        for (int j = 0; j < 15; ++j) {
            const int xx = j - 7;
            const double G = exp((double)(-(xx * xx + yy * yy)) / twosig2) / denomG;
            Gy[i * 15 + j] = ((double)(-yy) * G) / sig2;
        }
    }
    const double s = np_pairwise(Gy, 225);         // np.sum(Gy), numpy pairwise order

    Weights wt;
    for (int j = 0; j < 8; ++j) {
        const int xx = j - 7;
        wt.hw[j] = (float)(exp((double)(-(xx * xx)) / twosig2) / denomG);
    }
    for (int k = 0; k < 7; ++k) {
        const int yy = k - 7;
        const double A = (((double)(-yy) * exp((double)(-(yy * yy)) / twosig2)) / sig2) / s;
        wt.vw[k] = (float)A;
    }

    dim3 grid(TILES_Y, NB);
    gder_kernel<<<grid, 128>>>(x, wt, out);
}